// round 9
// baseline (speedup 1.0000x reference)
#include <cuda_runtime.h>
#include <cuda_fp16.h>
#include <cstdint>

// ---------------- model constants ----------------
#define BSZ      512
#define NCH      129
#define NT       250
#define DINNER   256
#define DSTATE   16
#define NHEADS   4
#define CONVDIM  288
#define DPROJ    548
#define EPSV     1e-5f
#define ROWH     544        // z(256)+xBC(288) stored as fp16 per row

// GEMM tiling: K = 128 (MMA) + 1 (rank-1 epilogue fixup)
#define TM     128
#define TN     72
#define TK     128
#define NJC    8
#define NKK    8
#define PITCHB 272
#define SPITCH 76

// ---------------- device scratch ----------------
__device__ float g_W[DPROJ * NCH];
__device__ float g_bias[DPROJ];
__device__ float g_v[DINNER];
__device__ __align__(16) __half g_zx[(size_t)BSZ * NT * ROWH];  // ~139 MB
__device__ __align__(16) float g_dt4[(size_t)BSZ * NT * 4];     // 2 MB
__device__ __align__(16) __half g_Wh[NJC * TN * TK];
__device__ float g_Wcol[576];
__device__ float g_biasP[576];

// ---------------- GEMM smem layout (bytes) ----------------
#define SM_AH    0                      // 128*272 = 34816
#define SM_BH    34816                  // 72*272  = 19584
#define SM_X128  54400
#define SM_W128  54912
#define SM_BIAS  55200
#define SMEM_SZ  55488

// ---------------- packed f32x2 helpers ----------------
typedef unsigned long long ull;
__device__ __forceinline__ ull dup2(float v) {
    ull r; asm("mov.b64 %0, {%1, %1};" : "=l"(r) : "f"(v)); return r;
}
__device__ __forceinline__ ull pack2(float lo, float hi) {
    ull r; asm("mov.b64 %0, {%1, %2};" : "=l"(r) : "f"(lo), "f"(hi)); return r;
}
__device__ __forceinline__ ull ffma2(ull a, ull b, ull c) {
    ull d; asm("fma.rn.f32x2 %0, %1, %2, %3;" : "=l"(d) : "l"(a), "l"(b), "l"(c)); return d;
}
__device__ __forceinline__ ull fmul2(ull a, ull b) {
    ull d; asm("mul.rn.f32x2 %0, %1, %2;" : "=l"(d) : "l"(a), "l"(b)); return d;
}
__device__ __forceinline__ float2 unpk2(ull v) {
    float2 f; asm("mov.b64 {%0, %1}, %2;" : "=f"(f.x), "=f"(f.y) : "l"(v)); return f;
}

// ---------------- mma / ldmatrix (base sm_103 PTX) ----------------
__device__ __forceinline__ void mma16816(float* d, const uint32_t* a, const uint32_t* b) {
    asm volatile(
        "mma.sync.aligned.m16n8k16.row.col.f32.f16.f16.f32 "
        "{%0,%1,%2,%3}, {%4,%5,%6,%7}, {%8,%9}, {%0,%1,%2,%3};"
        : "+f"(d[0]), "+f"(d[1]), "+f"(d[2]), "+f"(d[3])
        : "r"(a[0]), "r"(a[1]), "r"(a[2]), "r"(a[3]), "r"(b[0]), "r"(b[1]));
}
__device__ __forceinline__ void ldsm4(uint32_t* r, uint32_t addr) {
    asm volatile("ldmatrix.sync.aligned.m8n8.x4.shared.b16 {%0,%1,%2,%3}, [%4];"
        : "=r"(r[0]), "=r"(r[1]), "=r"(r[2]), "=r"(r[3]) : "r"(addr));
}
__device__ __forceinline__ void ldsm2(uint32_t* r, uint32_t addr) {
    asm volatile("ldmatrix.sync.aligned.m8n8.x2.shared.b16 {%0,%1}, [%2];"
        : "=r"(r[0]), "=r"(r[1]) : "r"(addr));
}
__device__ __forceinline__ uint32_t smem_u32(const void* p) {
    uint32_t a;
    asm("{ .reg .u64 t; cvta.to.shared.u64 t, %1; cvt.u32.u64 %0, t; }" : "=r"(a) : "l"(p));
    return a;
}

// =====================================================================
// prep1: fused weights
// =====================================================================
__global__ void prep1_kernel(const float* __restrict__ in_proj_w,
                             const float* __restrict__ mixer_w,
                             const float* __restrict__ mixer_b,
                             const float* __restrict__ out_proj_w,
                             const float* __restrict__ head_w) {
    int idx = blockIdx.x * blockDim.x + threadIdx.x;
    const int NW = DPROJ * NCH;
    if (idx < NW) {
        int j = idx / NCH, c = idx - j * NCH;
        float a0 = 0.f, a1 = 0.f, a2 = 0.f, a3 = 0.f;
        #pragma unroll 8
        for (int d = 0; d < 128; d += 4) {
            a0 = fmaf(in_proj_w[j * 128 + d + 0], mixer_w[(d + 0) * NCH + c], a0);
            a1 = fmaf(in_proj_w[j * 128 + d + 1], mixer_w[(d + 1) * NCH + c], a1);
            a2 = fmaf(in_proj_w[j * 128 + d + 2], mixer_w[(d + 2) * NCH + c], a2);
            a3 = fmaf(in_proj_w[j * 128 + d + 3], mixer_w[(d + 3) * NCH + c], a3);
        }
        g_W[idx] = (a0 + a1) + (a2 + a3);
    } else if (idx < NW + DPROJ) {
        int j = idx - NW;
        float acc = 0.f;
        #pragma unroll 4
        for (int d = 0; d < 128; d++)
            acc = fmaf(in_proj_w[j * 128 + d], mixer_b[d], acc);
        g_bias[j] = acc;
    } else if (idx < NW + DPROJ + DINNER) {
        int i = idx - NW - DPROJ;
        float acc = 0.f;
        #pragma unroll 4
        for (int d = 0; d < 128; d++)
            acc = fmaf(out_proj_w[d * DINNER + i], head_w[d], acc);
        g_v[i] = acc;
    }
}

// =====================================================================
// prep2: W (k<128) -> fp16 chunk tiles; pad Wcol/bias
// =====================================================================
__global__ void prep2_kernel() {
    int idx = blockIdx.x * blockDim.x + threadIdx.x;
    const int NH = NJC * TN * TK;
    if (idx < NH) {
        int k = idx & 127;
        int t = idx >> 7;
        int n = t % TN;
        int jc = t / TN;
        int j = jc * TN + n;
        float val = (j < DPROJ) ? g_W[j * NCH + k] : 0.f;
        g_Wh[idx] = __float2half(val);
    } else if (idx < NH + 576) {
        int j = idx - NH;
        g_Wcol[j] = (j < DPROJ) ? g_W[j * NCH + 128] : 0.f;
    } else if (idx < NH + 1152) {
        int j = idx - NH - 576;
        g_biasP[j] = (j < DPROJ) ? g_bias[j] : 0.f;
    }
}

// =====================================================================
// gemm_mma: single-pass fp16 GEMM; epilogue writes fp16 z/xBC + fp32 dt
// =====================================================================
__global__ void __launch_bounds__(256, 2) gemm_mma(const float* __restrict__ x) {
    extern __shared__ __align__(16) unsigned char sm[];
    const uint32_t sbase = smem_u32(sm);
    const int tid = threadIdx.x;
    const int wid = tid >> 5, lane = tid & 31;
    const int gid = lane >> 2, tig = lane & 3;
    const int tt = blockIdx.x, jc = blockIdx.y, b = blockIdx.z;
    const int t0 = tt * TM;

    {
        const unsigned char* src = (const unsigned char*)(g_Wh + (size_t)jc * (TN * TK));
        for (int i = tid; i < TN * 16; i += 256) {
            int n = i >> 4, q = i & 15;
            *(uint4*)(sm + SM_BH + n * PITCHB + q * 16) = *(const uint4*)(src + n * 256 + q * 16);
        }
    }
    {
        const float* xb = x + (size_t)b * (NCH * NT);
        for (int i = tid; i < 64 * TM; i += 256) {
            int cp = i >> 7, m = i & (TM - 1);
            int t = t0 + m;
            int c0 = 2 * cp;
            float v0 = (t < NT) ? xb[(size_t)c0 * NT + t] : 0.f;
            float v1 = (t < NT) ? xb[(size_t)(c0 + 1) * NT + t] : 0.f;
            uint32_t off = (uint32_t)m * PITCHB + (uint32_t)cp * 4;
            *(__half2*)(sm + SM_AH + off) = __half2{__float2half(v0), __float2half(v1)};
        }
    }
    if (tid < 128) {
        int t = t0 + tid;
        const float* xb = x + (size_t)b * (NCH * NT);
        *(float*)(sm + SM_X128 + tid * 4) = (t < NT) ? xb[(size_t)128 * NT + t] : 0.f;
        if (tid < TN) {
            *(float*)(sm + SM_W128 + tid * 4) = g_Wcol[jc * TN + tid];
            *(float*)(sm + SM_BIAS + tid * 4) = g_biasP[jc * TN + tid];
        }
    }
    __syncthreads();

    float acc[9][4];
    #pragma unroll
    for (int ni = 0; ni < 9; ni++)
        #pragma unroll
        for (int q = 0; q < 4; q++) acc[ni][q] = 0.f;

    const uint32_t aOff = (uint32_t)(wid * 16 + (lane & 15)) * PITCHB + (uint32_t)(lane >> 4) * 16;
    const uint32_t bOff = (uint32_t)(lane & 15) * PITCHB + (uint32_t)(lane >> 4) * 16;
    const uint32_t b2Off = (uint32_t)(64 + (lane & 7)) * PITCHB + (uint32_t)((lane >> 3) & 1) * 16;

    const uint32_t Ah = sbase + SM_AH + aOff;
    const uint32_t Bb = sbase + SM_BH + bOff;
    const uint32_t Bb2 = sbase + SM_BH + b2Off;

    #pragma unroll
    for (int kk = 0; kk < NKK; kk++) {
        uint32_t ah[4];
        ldsm4(ah, Ah + kk * 32);
        #pragma unroll
        for (int q = 0; q < 4; q++) {
            uint32_t bb[4];
            ldsm4(bb, Bb + (uint32_t)(q * 16) * PITCHB + kk * 32);
            uint32_t f0[2] = { bb[0], bb[2] };
            uint32_t f1[2] = { bb[1], bb[3] };
            mma16816(acc[2 * q],     ah, f0);
            mma16816(acc[2 * q + 1], ah, f1);
        }
        uint32_t b2[2];
        ldsm2(b2, Bb2 + kk * 32);
        mma16816(acc[8], ah, b2);
    }

    __syncthreads();
    float* stage = (float*)sm;
    {
        int r = wid * 16 + gid;
        #pragma unroll
        for (int ni = 0; ni < 9; ni++) {
            int c = ni * 8 + 2 * tig;
            *(float2*)(stage + r * SPITCH + c) = make_float2(acc[ni][0], acc[ni][1]);
            *(float2*)(stage + (r + 8) * SPITCH + c) = make_float2(acc[ni][2], acc[ni][3]);
        }
    }
    __syncthreads();

    const float* xs128 = (const float*)(sm + SM_X128);
    const float* sW = (const float*)(sm + SM_W128);
    const float* sBs = (const float*)(sm + SM_BIAS);
    for (int i = tid; i < TM * (TN / 4); i += 256) {
        int row = i / (TN / 4), q = i % (TN / 4);
        int t = t0 + row;
        int j = jc * TN + 4 * q;
        if (t < NT) {
            const float* sp = stage + row * SPITCH + 4 * q;
            float xk = xs128[row];
            float o0 = fmaf(xk, sW[4 * q + 0], sp[0] + sBs[4 * q + 0]);
            float o1 = fmaf(xk, sW[4 * q + 1], sp[1] + sBs[4 * q + 1]);
            float o2 = fmaf(xk, sW[4 * q + 2], sp[2] + sBs[4 * q + 2]);
            float o3 = fmaf(xk, sW[4 * q + 3], sp[3] + sBs[4 * q + 3]);
            if (j + 3 < ROWH) {
                __half2 ha = __floats2half2_rn(o0, o1);
                __half2 hb = __floats2half2_rn(o2, o3);
                uint2 pk = { *(uint32_t*)&ha, *(uint32_t*)&hb };
                *(uint2*)(g_zx + ((size_t)b * NT + t) * ROWH + j) = pk;
            } else if (j == ROWH) {   // dt block j=544..547
                *(float4*)(g_dt4 + ((size_t)b * NT + t) * 4) =
                    make_float4(o0, o1, o2, o3);
            }
        }
    }
}

// =====================================================================
// scan: 160 threads, 2ch/thread, fp16 inputs, 2 steps per barrier
//   (4-buffer rotation), deferred RMSNorm, direct out[b] write
// =====================================================================
__global__ void __launch_bounds__(160, 4)
scan_kernel(const float* __restrict__ conv_w, const float* __restrict__ conv_b,
            const float* __restrict__ dt_bias, const float* __restrict__ A_log,
            const float* __restrict__ Dp, const float* __restrict__ norm_w,
            const float* __restrict__ head_b, float* __restrict__ out) {
    const int b = blockIdx.x;
    const int tid = threadIdx.x;
    const int lane = tid & 31, wid = tid >> 5;
    const int c0 = 2 * tid;
    const int h = tid >> 5;

    __shared__ __align__(8) float2 sB2[4][DSTATE];
    __shared__ __align__(8) float2 sC2[4][DSTATE];
    __shared__ float sdA[4][NHEADS], sdt[4][NHEADS];
    __shared__ __align__(8) float2 sPS[NT][4];
    __shared__ float sfin[5];

    const bool isConv = (tid < 144);
    const bool isScan = (tid < 128);
    const bool isDt   = (tid >= 144 && tid < 148);

    ull wk0 = 0, wk1 = 0, wk2_ = 0, wk3 = 0, cb2 = 0;
    if (isConv) {
        wk0 = pack2(conv_w[c0 * 4 + 0], conv_w[(c0 + 1) * 4 + 0]);
        wk1 = pack2(conv_w[c0 * 4 + 1], conv_w[(c0 + 1) * 4 + 1]);
        wk2_ = pack2(conv_w[c0 * 4 + 2], conv_w[(c0 + 1) * 4 + 2]);
        wk3 = pack2(conv_w[c0 * 4 + 3], conv_w[(c0 + 1) * 4 + 3]);
        cb2 = pack2(conv_b[c0], conv_b[c0 + 1]);
    }
    ull h1 = 0ULL, h2 = 0ULL, h3 = 0ULL;

    float nw0 = 0.f, nw1 = 0.f, Dh = 0.f;
    if (isScan) {
        nw0 = norm_w[c0] * g_v[c0];
        nw1 = norm_w[c0 + 1] * g_v[c0 + 1];
        Dh = Dp[h];
    }
    float dtb = 0.f, Aneg = 0.f;
    if (isDt) { dtb = dt_bias[tid - 144]; Aneg = -expf(A_log[tid - 144]); }

    ull s2[DSTATE];
    #pragma unroll
    for (int n = 0; n < DSTATE; n++) s2[n] = 0ULL;

    const __half* zx = g_zx + (size_t)b * NT * ROWH;
    const float* dtp = g_dt4 + (size_t)b * NT * 4;

    // prefetch steps 0, 1
    __half2 rawA = __half2{}, rawB = __half2{};
    __half2 zhA = __half2{}, zhB = __half2{};
    float dtrA = 0.f, dtrB = 0.f;
    if (isConv) {
        rawA = *(const __half2*)(zx + 256 + c0);
        rawB = *(const __half2*)(zx + ROWH + 256 + c0);
    }
    if (isScan) {
        zhA = *(const __half2*)(zx + c0);
        zhB = *(const __half2*)(zx + ROWH + c0);
    }
    if (isDt) { dtrA = dtp[tid - 144]; dtrB = dtp[4 + (tid - 144)]; }

    for (int it = 0; it < NT / 2; it++) {
        const int t = 2 * it;
        const int bufA = (it & 1) * 2, bufB = bufA + 1;

        // ---- producers: conv+silu for both steps ----
        float csA0 = 0.f, csA1 = 0.f, csB0 = 0.f, csB1 = 0.f;
        if (isConv) {
            float2 fA = __half22float2(rawA);
            ull rA = pack2(fA.x, fA.y);
            ull cvA = ffma2(wk3, rA, ffma2(wk2_, h1, ffma2(wk1, h2, ffma2(wk0, h3, cb2))));
            h3 = h2; h2 = h1; h1 = rA;
            float2 cA = unpk2(cvA);
            csA0 = __fdividef(cA.x, 1.f + __expf(-cA.x));
            csA1 = __fdividef(cA.y, 1.f + __expf(-cA.y));

            float2 fB = __half22float2(rawB);
            ull rB = pack2(fB.x, fB.y);
            ull cvB = ffma2(wk3, rB, ffma2(wk2_, h1, ffma2(wk1, h2, ffma2(wk0, h3, cb2))));
            h3 = h2; h2 = h1; h1 = rB;
            float2 cB = unpk2(cvB);
            csB0 = __fdividef(cB.x, 1.f + __expf(-cB.x));
            csB1 = __fdividef(cB.y, 1.f + __expf(-cB.y));

            if (tid >= 128) {
                if (tid < 136) {
                    int k = 2 * (tid - 128);
                    sB2[bufA][k]     = make_float2(csA0, csA0);
                    sB2[bufA][k + 1] = make_float2(csA1, csA1);
                    sB2[bufB][k]     = make_float2(csB0, csB0);
                    sB2[bufB][k + 1] = make_float2(csB1, csB1);
                } else {
                    int k = 2 * (tid - 136);
                    sC2[bufA][k]     = make_float2(csA0, csA0);
                    sC2[bufA][k + 1] = make_float2(csA1, csA1);
                    sC2[bufB][k]     = make_float2(csB0, csB0);
                    sC2[bufB][k + 1] = make_float2(csB1, csB1);
                }
            }
        }
        if (isDt) {
            int q = tid - 144;
            float rvA = dtrA + dtb;
            float dA_ = (rvA > 15.f) ? rvA : __logf(1.f + __expf(rvA));
            sdt[bufA][q] = dA_;
            sdA[bufA][q] = __expf(dA_ * Aneg);
            float rvB = dtrB + dtb;
            float dB_ = (rvB > 15.f) ? rvB : __logf(1.f + __expf(rvB));
            sdt[bufB][q] = dB_;
            sdA[bufB][q] = __expf(dB_ * Aneg);
        }

        // ---- z gates (independent of smem) ----
        float gzA0 = 0.f, gzA1 = 0.f, gzB0 = 0.f, gzB1 = 0.f;
        if (isScan) {
            float2 zA = __half22float2(zhA);
            float2 zB = __half22float2(zhB);
            gzA0 = __fdividef(zA.x, 1.f + __expf(-zA.x));
            gzA1 = __fdividef(zA.y, 1.f + __expf(-zA.y));
            gzB0 = __fdividef(zB.x, 1.f + __expf(-zB.x));
            gzB1 = __fdividef(zB.y, 1.f + __expf(-zB.y));
        }

        // ---- prefetch t+2, t+3 ----
        __half2 nrawA = __half2{}, nrawB = __half2{};
        __half2 nzhA = __half2{}, nzhB = __half2{};
        float ndtrA = 0.f, ndtrB = 0.f;
        if (t + 2 < NT) {
            const __half* r2 = zx + (size_t)(t + 2) * ROWH;
            const __half* r3 = r2 + ROWH;
            if (isConv) {
                nrawA = *(const __half2*)(r2 + 256 + c0);
                nrawB = *(const __half2*)(r3 + 256 + c0);
            }
            if (isScan) {
                nzhA = *(const __half2*)(r2 + c0);
                nzhB = *(const __half2*)(r3 + c0);
            }
            if (isDt) {
                ndtrA = dtp[(t + 2) * 4 + (tid - 144)];
                ndtrB = dtp[(t + 3) * 4 + (tid - 144)];
            }
        }
        __syncthreads();

        if (isScan) {
            // ---- step A state update ----
            float dtvA = sdt[bufA][h];
            ull dA2A = dup2(sdA[bufA][h]);
            ull dx2A = pack2(dtvA * csA0, dtvA * csA1);
            ull yA = fmul2(dup2(Dh), pack2(csA0, csA1));
            #pragma unroll
            for (int n = 0; n < DSTATE; n++) {
                s2[n] = ffma2(s2[n], dA2A, fmul2(dx2A, *(const ull*)&sB2[bufA][n]));
                yA = ffma2(s2[n], *(const ull*)&sC2[bufA][n], yA);
            }
            float2 yyA = unpk2(yA);
            float g0A = yyA.x * gzA0;
            float g1A = yyA.y * gzA1;

            // ---- step B state update ----
            float dtvB = sdt[bufB][h];
            ull dA2B = dup2(sdA[bufB][h]);
            ull dx2B = pack2(dtvB * csB0, dtvB * csB1);
            ull yB = fmul2(dup2(Dh), pack2(csB0, csB1));
            #pragma unroll
            for (int n = 0; n < DSTATE; n++) {
                s2[n] = ffma2(s2[n], dA2B, fmul2(dx2B, *(const ull*)&sB2[bufB][n]));
                yB = ffma2(s2[n], *(const ull*)&sC2[bufB][n], yB);
            }
            float2 yyB = unpk2(yB);
            float g0B = yyB.x * gzB0;
            float g1B = yyB.y * gzB1;

            // ---- interleaved reductions (4 independent chains) ----
            float ssA = fmaf(g0A, g0A, g1A * g1A);
            float pA  = fmaf(g0A, nw0, g1A * nw1);
            float ssB = fmaf(g0B, g0B, g1B * g1B);
            float pB  = fmaf(g0B, nw0, g1B * nw1);
            #pragma unroll
            for (int o = 16; o > 0; o >>= 1) {
                ssA += __shfl_xor_sync(0xffffffffu, ssA, o);
                pA  += __shfl_xor_sync(0xffffffffu, pA, o);
                ssB += __shfl_xor_sync(0xffffffffu, ssB, o);
                pB  += __shfl_xor_sync(0xffffffffu, pB, o);
            }
            if (lane == 0) {
                sPS[t][wid]     = make_float2(ssA, pA);
                sPS[t + 1][wid] = make_float2(ssB, pB);
            }
        }

        rawA = nrawA; rawB = nrawB;
        zhA = nzhA; zhB = nzhB;
        dtrA = ndtrA; dtrB = ndtrB;
    }

    // final phase: deferred rsqrt per timestep
    __syncthreads();
    float facc = 0.f;
    for (int t = tid; t < NT; t += 160) {
        float2 a = sPS[t][0], b2 = sPS[t][1], c = sPS[t][2], d = sPS[t][3];
        float SS = (a.x + b2.x) + (c.x + d.x);
        float P  = (a.y + b2.y) + (c.y + d.y);
        facc = fmaf(P, rsqrtf(SS * (1.f / 256.f) + EPSV), facc);
    }
    #pragma unroll
    for (int o = 16; o > 0; o >>= 1) facc += __shfl_xor_sync(0xffffffffu, facc, o);
    if (lane == 0) sfin[wid] = facc;
    __syncthreads();
    if (tid == 0) {
        float tot = (sfin[0] + sfin[1]) + (sfin[2] + sfin[3]) + sfin[4];
        out[b] = tot * (1.f / (float)NT) + head_b[0];
    }
}

// =====================================================================
// launch
// =====================================================================
extern "C" void kernel_launch(void* const* d_in, const int* in_sizes, int n_in,
                              void* d_out, int out_size) {
    const float* x          = (const float*)d_in[0];
    const float* mixer_w    = (const float*)d_in[1];
    const float* mixer_b    = (const float*)d_in[2];
    const float* in_proj_w  = (const float*)d_in[3];
    const float* conv_w     = (const float*)d_in[4];
    const float* conv_b     = (const float*)d_in[5];
    const float* dt_bias    = (const float*)d_in[6];
    const float* A_log      = (const float*)d_in[7];
    const float* Dvec       = (const float*)d_in[8];
    const float* norm_w     = (const float*)d_in[9];
    const float* out_proj_w = (const float*)d_in[10];
    const float* head_w     = (const float*)d_in[11];
    const float* head_b     = (const float*)d_in[12];
    float* out = (float*)d_out;

    {
        int total = DPROJ * NCH + DPROJ + DINNER;
        prep1_kernel<<<(total + 255) / 256, 256>>>(in_proj_w, mixer_w, mixer_b,
                                                   out_proj_w, head_w);
    }
    {
        int total = NJC * TN * TK + 1152;
        prep2_kernel<<<(total + 255) / 256, 256>>>();
    }
    {
        cudaFuncSetAttribute(gemm_mma,
                             cudaFuncAttributeMaxDynamicSharedMemorySize, SMEM_SZ);
        dim3 grid(2, NJC, BSZ);
        gemm_mma<<<grid, 256, SMEM_SZ>>>(x);
    }
    scan_kernel<<<BSZ, 160>>>(conv_w, conv_b, dt_bias, A_log, Dvec,
                              norm_w, head_b, out);
}